// round 15
// baseline (speedup 1.0000x reference)
#include <cuda_runtime.h>
#include <math.h>
#include <stdint.h>

#define BB 16
#define CC 3
#define TT 32
#define HH 224
#define WW 224
#define GS 32
#define GH 7
#define GW 7
#define NPF 49
#define NODES 1568
#define NPATCH 25088
#define NPP 3072
#define NEDGE 15962
#define XFLOATS 250880
#define CAP 288
#define SUBCAP 64
#define PPB 4
#define GUARD 22.0f
#define CHS 1605632u     // channel stride in elements (32*224*224)

// fixed tight windows: quantile value +/- 3.5 sigma_q for N(0,1), n=3072
#define W0LO (-0.7606f)
#define W0HI (-0.5884f)
#define W1LO (-0.0791f)
#define W1HI ( 0.0791f)
#define W2LO ( 0.5884f)
#define W2HI ( 0.7606f)

__device__ __forceinline__ float wsumf(float x) {
    #pragma unroll
    for (int o = 16; o; o >>= 1) x += __shfl_xor_sync(0xffffffffu, x, o);
    return x;
}
__device__ __forceinline__ int wsumi(int x) {
    #pragma unroll
    for (int o = 16; o; o >>= 1) x += __shfl_xor_sync(0xffffffffu, x, o);
    return x;
}
__device__ __forceinline__ float wminf(float x) {
    #pragma unroll
    for (int o = 16; o; o >>= 1) x = fminf(x, __shfl_xor_sync(0xffffffffu, x, o));
    return x;
}
__device__ __forceinline__ float wmaxf(float x) {
    #pragma unroll
    for (int o = 16; o; o >>= 1) x = fmaxf(x, __shfl_xor_sync(0xffffffffu, x, o));
    return x;
}

__device__ __forceinline__ uint32_t xform(float f) {
    uint32_t u = __float_as_uint(f);
    return (u & 0x80000000u) ? ~u : (u | 0x80000000u);
}
__device__ __forceinline__ float unxform(uint32_t u) {
    u = (u & 0x80000000u) ? (u ^ 0x80000000u) : ~u;
    return __uint_as_float(u);
}

// packed f32x2 helpers
__device__ __forceinline__ uint64_t pk2(float a, float b) {
    uint64_t r; asm("mov.b64 %0,{%1,%2};" : "=l"(r) : "f"(a), "f"(b)); return r;
}
__device__ __forceinline__ void upk2(uint64_t p, float& a, float& b) {
    asm("mov.b64 {%0,%1},%2;" : "=f"(a), "=f"(b) : "l"(p));
}
__device__ __forceinline__ uint64_t add2(uint64_t a, uint64_t b) {
    uint64_t r; asm("add.rn.f32x2 %0,%1,%2;" : "=l"(r) : "l"(a), "l"(b)); return r;
}
__device__ __forceinline__ uint64_t mul2(uint64_t a, uint64_t b) {
    uint64_t r; asm("mul.rn.f32x2 %0,%1,%2;" : "=l"(r) : "l"(a), "l"(b)); return r;
}
__device__ __forceinline__ uint64_t fma2(uint64_t a, uint64_t b, uint64_t c) {
    uint64_t r; asm("fma.rn.f32x2 %0,%1,%2,%3;" : "=l"(r) : "l"(a), "l"(b), "l"(c)); return r;
}

// exact count of xform(x) <= code over the patch (gmem; cold path)
__device__ __noinline__ int count_le_code(const float* __restrict__ v, uint32_t base0,
                                          int rg, uint32_t code) {
    int c = 0;
    for (int k = 0; k < 24; k++) {
        int r = k * 4 + rg;
        uint32_t idx = base0 + (uint32_t)(r >> 5) * CHS + (uint32_t)(r & 31) * 224u;
        float4 x4 = *reinterpret_cast<const float4*>(v + idx);
        c += (xform(x4.x) <= code) + (xform(x4.y) <= code)
           + (xform(x4.z) <= code) + (xform(x4.w) <= code);
    }
    return wsumi(c);
}

// guaranteed-exact rank select via bisection over float code space (cold path)
__device__ __noinline__ float slow_rank(const float* __restrict__ v, uint32_t base0,
                                        int rg, int r) {
    uint32_t lo = 0u, hi = 0xFFFFFFFFu;
    while (lo < hi) {
        uint32_t mid = lo + ((hi - lo) >> 1);
        int c = count_le_code(v, base0, rg, mid);
        if (c >= r + 1) hi = mid; else lo = mid + 1;
    }
    return unxform(lo);
}

// exact tie-aware select of two ranks in buf[0..cnt), broadcast (cold fallback)
__device__ __noinline__ void select2c(const float* buf, int cnt, int rr0, int rr1,
                                      int lane, float* o0, float* o1) {
    float a0 = 0.f, a1 = 0.f;
    bool f0 = false, f1 = false;
    for (int base = 0; base < cnt; base += 32) {
        int idx = base + lane;
        float key = (idx < cnt) ? buf[idx] : 0.f;
        int less = 0, eq = 0;
        for (int m = 0; m < cnt; m++) {
            float c = buf[m];
            less += (c < key);
            eq   += (c == key);
        }
        if (idx < cnt) {
            if (rr0 >= less && rr0 < less + eq) { a0 = key; f0 = true; }
            if (rr1 >= less && rr1 < less + eq) { a1 = key; f1 = true; }
        }
    }
    unsigned m0 = __ballot_sync(0xffffffffu, f0);
    unsigned m1 = __ballot_sync(0xffffffffu, f1);
    int s0 = m0 ? (__ffs(m0) - 1) : 0;
    int s1 = m1 ? (__ffs(m1) - 1) : 0;
    *o0 = __shfl_sync(0xffffffffu, a0, s0);
    *o1 = __shfl_sync(0xffffffffu, a1, s1);
}

// bitonic sort of 64 values: a at index lane, b at index lane+32, ascending
__device__ __forceinline__ void bitonic64(float& a, float& b, int lane) {
    #pragma unroll
    for (int k = 2; k <= 32; k <<= 1) {
        #pragma unroll
        for (int j = k >> 1; j >= 1; j >>= 1) {
            {
                float pa = __shfl_xor_sync(0xffffffffu, a, j);
                bool up = ((lane & k) == 0);
                bool lower = ((lane & j) == 0);
                a = (lower == up) ? fminf(a, pa) : fmaxf(a, pa);
            }
            {
                float pb = __shfl_xor_sync(0xffffffffu, b, j);
                bool up = (k == 32) ? false : ((lane & k) == 0);
                bool lower = ((lane & j) == 0);
                b = (lower == up) ? fminf(b, pb) : fmaxf(b, pb);
            }
        }
    }
    {
        float lo = fminf(a, b), hi = fmaxf(a, b);
        a = lo; b = hi;
    }
    #pragma unroll
    for (int j = 16; j >= 1; j >>= 1) {
        {
            float pa = __shfl_xor_sync(0xffffffffu, a, j);
            bool lower = ((lane & j) == 0);
            a = lower ? fminf(a, pa) : fmaxf(a, pa);
        }
        {
            float pb = __shfl_xor_sync(0xffffffffu, b, j);
            bool lower = ((lane & j) == 0);
            b = lower ? fminf(b, pb) : fmaxf(b, pb);
        }
    }
}
__device__ __forceinline__ float sorted_at(float a, float b, int r) {
    float va = __shfl_sync(0xffffffffu, a, r & 31);
    float vb = __shfl_sync(0xffffffffu, b, r & 31);
    return (r < 32) ? va : vb;
}

__global__ void __launch_bounds__(32 * PPB, 14)
feat_kernel(const float* __restrict__ v, float* __restrict__ out)
{
    __shared__ float cbuf[PPB][3][CAP];
    __shared__ float sbuf[PPB][SUBCAP];
    __shared__ int   dcur[PPB][3];

    const int lane = threadIdx.x & 31;
    const int warp = threadIdx.x >> 5;
    const int p = blockIdx.x * PPB + warp;
    const int j = p % GW;
    int tmp = p / GW;
    const int i = tmp % GH;
    tmp /= GH;
    const int t = tmp % TT;
    const int b = tmp / TT;

    const int sub = lane & 7, rg = lane >> 3;
    const uint32_t base0 = (uint32_t)(b * CC * TT + t) * 50176u
                         + (uint32_t)(i * GS) * 224u + (uint32_t)(j * GS)
                         + (uint32_t)(sub * 4);

    const float WLO[3] = {W0LO, W1LO, W2LO};
    const float WHI[3] = {W0HI, W1HI, W2HI};
    const int RMIN[3] = {767, 1535, 2303};
    const int RMAX[3] = {768, 1535, 2304};

    if (lane < 3) dcur[warp][lane] = 0;
    __syncwarp();

    // ---- single fused pass: packed moments + min/max + counts + precise gather ----
    uint64_t S1p = 0, S2p = 0, S3p = 0, S4p = 0;
    float mn = INFINITY, mx = -INFINITY;
    int c0 = 0, c1 = 0, c2 = 0;
    #pragma unroll 4
    for (int k = 0; k < 24; k++) {
        int r = k * 4 + rg;
        uint32_t idx = base0 + (uint32_t)(r >> 5) * CHS + (uint32_t)(r & 31) * 224u;
        float4 x4 = __ldcs(reinterpret_cast<const float4*>(v + idx));

        uint64_t pA = pk2(x4.x, x4.y), pB = pk2(x4.z, x4.w);
        uint64_t qA = mul2(pA, pA), qB = mul2(pB, pB);
        S1p = add2(S1p, pA); S1p = add2(S1p, pB);
        S2p = add2(S2p, qA); S2p = add2(S2p, qB);
        S3p = fma2(qA, pA, S3p); S3p = fma2(qB, pB, S3p);
        S4p = fma2(qA, qA, S4p); S4p = fma2(qB, qB, S4p);

        float xs[4] = {x4.x, x4.y, x4.z, x4.w};
        #pragma unroll
        for (int e = 0; e < 4; e++) {
            float x = xs[e];
            mn = fminf(mn, x);
            mx = fmaxf(mx, x);
            bool l0 = x < W0LO; c0 += l0;
            bool l1 = x < W1LO; c1 += l1;
            bool l2 = x < W2LO; c2 += l2;
            bool in0 = (!l0) && (x < W0HI);
            bool in1 = (!l1) && (x < W1HI);
            bool in2 = (!l2) && (x < W2HI);
            if (in0 | in1 | in2) {                 // ~17% entry rate
                int wsel = in1 ? 1 : (in0 ? 0 : 2);
                int pos = atomicAdd(&dcur[warp][wsel], 1);
                if (pos < CAP) cbuf[warp][wsel][pos] = x;
            }
        }
    }
    float s1a, s1b, s2a, s2b, s3a, s3b, s4a, s4b;
    upk2(S1p, s1a, s1b); upk2(S2p, s2a, s2b);
    upk2(S3p, s3a, s3b); upk2(S4p, s4a, s4b);
    float S1 = wsumf(s1a + s1b), S2 = wsumf(s2a + s2b);
    float S3 = wsumf(s3a + s3b), S4 = wsumf(s4a + s4b);
    mn = wminf(mn); mx = wmaxf(mx);
    int pk = wsumi(c0 | (c1 << 16));
    c2 = wsumi(c2);
    int cla[3] = {pk & 0xFFFF, pk >> 16, c2};
    __syncwarp();

    // ---- per-window smem refinement + sort-based exact select ----
    float ql[3], qh[3];
    const unsigned ltm = (1u << lane) - 1u;
    #pragma unroll
    for (int w = 0; w < 3; w++) {
        const int g = dcur[warp][w];
        const int rmin = RMIN[w], rmax = RMAX[w];
        const int cl = cla[w];
        if (g <= CAP && cl <= rmin && rmax < cl + g) {
            float span = WHI[w] - WLO[w];
            float inv = span / (float)g;
            float plo2 = WLO[w] + ((float)rmin - GUARD - (float)cl) * inv;
            float phi2 = WLO[w] + ((float)rmax + GUARD + 1.0f - (float)cl) * inv;
            plo2 = fmaxf(plo2, WLO[w]);
            phi2 = fminf(phi2, WHI[w]);

            const float* bw = cbuf[warp][w];
            int elo = 0, sc = 0;
            #pragma unroll 3
            for (int bidx = 0; bidx < g; bidx += 32) {
                int idx = bidx + lane;
                bool val = idx < g;
                float x = val ? bw[idx] : 0.f;
                elo += val && (x < plo2);
                bool inb = val && (x >= plo2) && (x < phi2);
                unsigned mk = __ballot_sync(0xffffffffu, inb);
                if (inb) {
                    int pos = sc + __popc(mk & ltm);
                    if (pos < SUBCAP) sbuf[warp][pos] = x;
                }
                sc += __popc(mk);
            }
            elo = wsumi(elo);
            __syncwarp();
            int basr = cl + elo;
            if (sc <= SUBCAP && basr <= rmin && rmax < basr + sc) {
                float aa = (lane < sc) ? sbuf[warp][lane] : INFINITY;
                float bb = (lane + 32 < sc) ? sbuf[warp][lane + 32] : INFINITY;
                bitonic64(aa, bb, lane);
                ql[w] = sorted_at(aa, bb, rmin - basr);
                qh[w] = sorted_at(aa, bb, rmax - basr);
            } else {
                select2c(bw, g, rmin - cl, rmax - cl, lane, &ql[w], &qh[w]);
            }
            __syncwarp();
        } else {
            ql[w] = slow_rank(v, base0, rg, rmin);
            qh[w] = (rmax == rmin) ? ql[w] : slow_rank(v, base0, rg, rmax);
        }
    }

    if (lane == 0) {
        const double n = (double)NPP;
        double s1 = S1, s2 = S2, s3 = S3, s4 = S4;
        double mean = s1 / n;
        double c2m = s2 - n * mean * mean;
        double c3m = s3 - 3.0 * mean * s2 + 2.0 * n * mean * mean * mean;
        double m2s = mean * mean;
        double c4m = s4 - 4.0 * mean * s3 + 6.0 * m2s * s2 - 3.0 * n * m2s * m2s;
        double sd = sqrt(c2m / (n - 1.0));
        double sde = sd + 1e-8;
        double energy = s2 / n;
        double rms = sqrt(energy + 1e-8);
        double i3 = 1.0 / (sde * sde * sde);
        double skew = (c3m / n) * i3;
        double kurt = (c4m / n) * i3 / sde - 3.0;
        float q25 = ql[0] * 0.25f + qh[0] * 0.75f;
        float q75 = ql[2] * 0.75f + qh[2] * 0.25f;

        float* o = out + (size_t)p * 10;
        o[0] = (float)mean; o[1] = (float)sd; o[2] = mn; o[3] = mx;
        o[4] = (float)energy; o[5] = (float)rms; o[6] = (float)skew;
        o[7] = (float)kurt; o[8] = ql[1]; o[9] = q75 - q25;
    }
}

__device__ __forceinline__ int tau_t(int t) {
    int c = 0;
    if (t + 1 < TT) c++;
    if (t - 1 >= 0) c++;
    if (t + 2 < TT) c++;
    if (t - 2 >= 0) c++;
    return c;
}

__global__ void edge_kernel(float* __restrict__ out)
{
    int node = blockIdx.x * blockDim.x + threadIdx.x;
    if (node >= NODES) return;
    int t = node / NPF;
    int rem = node % NPF;
    int i = rem / GW;
    int j = rem % GW;

    int mt = t < 30 ? t : 30;
    int cum_tau = (t > 0 ? 2 : 0) + (t > 1 ? 3 : 0)
                + 4 * (mt > 2 ? (mt - 2) : 0) + (t > 30 ? 3 : 0);
    int taut = tau_t(t);
    int rowpref = (i == 0) ? 0 : (31 + 50 * (i - 1));
    int ci = (i == 0 || i == GH - 1) ? 2 : 3;
    int cumcj = (j > 0 ? 2 : 0) + 3 * (j > 1 ? (j - 1) : 0);
    int sp = rowpref + ci * cumcj - j;
    int off = 312 * t + 49 * cum_tau + sp + rem * taut;

    const int di[8] = {-1,-1,-1, 0, 0, 1, 1, 1};
    const int dj[8] = {-1, 0, 1,-1, 1,-1, 0, 1};
    int e = off;
    float fnode = (float)node;
    #pragma unroll
    for (int q = 0; q < 8; q++) {
        int ni = i + di[q], nj = j + dj[q];
        if (ni >= 0 && ni < GH && nj >= 0 && nj < GW) {
            out[e]         = fnode;
            out[NEDGE + e] = (float)(t * NPF + ni * GW + nj);
            e++;
        }
    }
    const int dts[4] = {1, -1, 2, -2};
    #pragma unroll
    for (int q = 0; q < 4; q++) {
        int tt2 = t + dts[q];
        if (tt2 >= 0 && tt2 < TT) {
            out[e]         = fnode;
            out[NEDGE + e] = (float)(tt2 * NPF + i * GW + j);
            e++;
        }
    }
}

extern "C" void kernel_launch(void* const* d_in, const int* in_sizes, int n_in,
                              void* d_out, int out_size)
{
    const float* video = (const float*)d_in[0];
    float* out = (float*)d_out;

    if (out_size >= XFLOATS + 2 * NEDGE) {
        edge_kernel<<<(NODES + 255) / 256, 256>>>(out + XFLOATS);
    }
    feat_kernel<<<NPATCH / PPB, 32 * PPB>>>(video, out);
}

// round 16
// speedup vs baseline: 1.5807x; 1.5807x over previous
#include <cuda_runtime.h>
#include <math.h>
#include <stdint.h>

#define BB 16
#define CC 3
#define TT 32
#define HH 224
#define WW 224
#define GS 32
#define GH 7
#define GW 7
#define NPF 49
#define NODES 1568
#define NPATCH 25088
#define NPP 3072
#define NEDGE 15962
#define XFLOATS 250880
#define SEGC 144
#define CAP (2 * SEGC)
#define SUBCAP 64
#define PPB 4
#define GUARD 22.0f
#define CHS 1605632u     // channel stride in elements (32*224*224)

// fixed tight windows: quantile value +/- 3.5 sigma_q for N(0,1), n=3072
#define W0LO (-0.7606f)
#define W0HI (-0.5884f)
#define W1LO (-0.0791f)
#define W1HI ( 0.0791f)
#define W2LO ( 0.5884f)
#define W2HI ( 0.7606f)

__device__ __forceinline__ float wsumf(float x) {
    #pragma unroll
    for (int o = 16; o; o >>= 1) x += __shfl_xor_sync(0xffffffffu, x, o);
    return x;
}
__device__ __forceinline__ int wsumi(int x) {
    #pragma unroll
    for (int o = 16; o; o >>= 1) x += __shfl_xor_sync(0xffffffffu, x, o);
    return x;
}
__device__ __forceinline__ float wminf(float x) {
    #pragma unroll
    for (int o = 16; o; o >>= 1) x = fminf(x, __shfl_xor_sync(0xffffffffu, x, o));
    return x;
}
__device__ __forceinline__ float wmaxf(float x) {
    #pragma unroll
    for (int o = 16; o; o >>= 1) x = fmaxf(x, __shfl_xor_sync(0xffffffffu, x, o));
    return x;
}

__device__ __forceinline__ uint32_t xform(float f) {
    uint32_t u = __float_as_uint(f);
    return (u & 0x80000000u) ? ~u : (u | 0x80000000u);
}
__device__ __forceinline__ float unxform(uint32_t u) {
    u = (u & 0x80000000u) ? (u ^ 0x80000000u) : ~u;
    return __uint_as_float(u);
}

// packed f32x2 helpers
__device__ __forceinline__ uint64_t pk2(float a, float b) {
    uint64_t r; asm("mov.b64 %0,{%1,%2};" : "=l"(r) : "f"(a), "f"(b)); return r;
}
__device__ __forceinline__ void upk2(uint64_t p, float& a, float& b) {
    asm("mov.b64 {%0,%1},%2;" : "=f"(a), "=f"(b) : "l"(p));
}
__device__ __forceinline__ uint64_t add2(uint64_t a, uint64_t b) {
    uint64_t r; asm("add.rn.f32x2 %0,%1,%2;" : "=l"(r) : "l"(a), "l"(b)); return r;
}
__device__ __forceinline__ uint64_t mul2(uint64_t a, uint64_t b) {
    uint64_t r; asm("mul.rn.f32x2 %0,%1,%2;" : "=l"(r) : "l"(a), "l"(b)); return r;
}
__device__ __forceinline__ uint64_t fma2(uint64_t a, uint64_t b, uint64_t c) {
    uint64_t r; asm("fma.rn.f32x2 %0,%1,%2,%3;" : "=l"(r) : "l"(a), "l"(b), "l"(c)); return r;
}

// exact count of xform(x) <= code over the patch (gmem; cold path)
__device__ __noinline__ int count_le_code(const float* __restrict__ v, uint32_t base0,
                                          int rg, uint32_t code) {
    int c = 0;
    for (int k = 0; k < 24; k++) {
        int r = k * 4 + rg;
        uint32_t idx = base0 + (uint32_t)(r >> 5) * CHS + (uint32_t)(r & 31) * 224u;
        float4 x4 = *reinterpret_cast<const float4*>(v + idx);
        c += (xform(x4.x) <= code) + (xform(x4.y) <= code)
           + (xform(x4.z) <= code) + (xform(x4.w) <= code);
    }
    return wsumi(c);
}

// guaranteed-exact rank select via bisection over float code space (cold path)
__device__ __noinline__ float slow_rank(const float* __restrict__ v, uint32_t base0,
                                        int rg, int r) {
    uint32_t lo = 0u, hi = 0xFFFFFFFFu;
    while (lo < hi) {
        uint32_t mid = lo + ((hi - lo) >> 1);
        int c = count_le_code(v, base0, rg, mid);
        if (c >= r + 1) hi = mid; else lo = mid + 1;
    }
    return unxform(lo);
}

// exact tie-aware select of two ranks in buf[0..cnt), broadcast (cold fallback)
__device__ __noinline__ void select2c(const float* buf, int cnt, int rr0, int rr1,
                                      int lane, float* o0, float* o1) {
    float a0 = 0.f, a1 = 0.f;
    bool f0 = false, f1 = false;
    for (int base = 0; base < cnt; base += 32) {
        int idx = base + lane;
        float key = (idx < cnt) ? buf[idx] : 0.f;
        int less = 0, eq = 0;
        for (int m = 0; m < cnt; m++) {
            float c = buf[m];
            less += (c < key);
            eq   += (c == key);
        }
        if (idx < cnt) {
            if (rr0 >= less && rr0 < less + eq) { a0 = key; f0 = true; }
            if (rr1 >= less && rr1 < less + eq) { a1 = key; f1 = true; }
        }
    }
    unsigned m0 = __ballot_sync(0xffffffffu, f0);
    unsigned m1 = __ballot_sync(0xffffffffu, f1);
    int s0 = m0 ? (__ffs(m0) - 1) : 0;
    int s1 = m1 ? (__ffs(m1) - 1) : 0;
    *o0 = __shfl_sync(0xffffffffu, a0, s0);
    *o1 = __shfl_sync(0xffffffffu, a1, s1);
}

// bitonic sort of 64 values: a at index lane, b at index lane+32, ascending
__device__ __forceinline__ void bitonic64(float& a, float& b, int lane) {
    #pragma unroll
    for (int k = 2; k <= 32; k <<= 1) {
        #pragma unroll
        for (int j = k >> 1; j >= 1; j >>= 1) {
            {
                float pa = __shfl_xor_sync(0xffffffffu, a, j);
                bool up = ((lane & k) == 0);
                bool lower = ((lane & j) == 0);
                a = (lower == up) ? fminf(a, pa) : fmaxf(a, pa);
            }
            {
                float pb = __shfl_xor_sync(0xffffffffu, b, j);
                bool up = (k == 32) ? false : ((lane & k) == 0);
                bool lower = ((lane & j) == 0);
                b = (lower == up) ? fminf(b, pb) : fmaxf(b, pb);
            }
        }
    }
    {
        float lo = fminf(a, b), hi = fmaxf(a, b);
        a = lo; b = hi;
    }
    #pragma unroll
    for (int j = 16; j >= 1; j >>= 1) {
        {
            float pa = __shfl_xor_sync(0xffffffffu, a, j);
            bool lower = ((lane & j) == 0);
            a = lower ? fminf(a, pa) : fmaxf(a, pa);
        }
        {
            float pb = __shfl_xor_sync(0xffffffffu, b, j);
            bool lower = ((lane & j) == 0);
            b = lower ? fminf(b, pb) : fmaxf(b, pb);
        }
    }
}
__device__ __forceinline__ float sorted_at(float a, float b, int r) {
    float va = __shfl_sync(0xffffffffu, a, r & 31);
    float vb = __shfl_sync(0xffffffffu, b, r & 31);
    return (r < 32) ? va : vb;
}

__global__ void __launch_bounds__(32 * PPB, 12)
feat_kernel(const float* __restrict__ v, float* __restrict__ out)
{
    __shared__ float cbuf[PPB][3][CAP];
    __shared__ float sbuf[PPB][SUBCAP];
    __shared__ int   dcur[PPB][6];

    const int lane = threadIdx.x & 31;
    const int warp = threadIdx.x >> 5;
    const int p = blockIdx.x * PPB + warp;
    const int j = p % GW;
    int tmp = p / GW;
    const int i = tmp % GH;
    tmp /= GH;
    const int t = tmp % TT;
    const int b = tmp / TT;

    const int sub = lane & 7, rg = lane >> 3;
    const uint32_t base0 = (uint32_t)(b * CC * TT + t) * 50176u
                         + (uint32_t)(i * GS) * 224u + (uint32_t)(j * GS)
                         + (uint32_t)(sub * 4);

    const float WLO[3] = {W0LO, W1LO, W2LO};
    const float WHI[3] = {W0HI, W1HI, W2HI};
    const int RMIN[3] = {767, 1535, 2303};
    const int RMAX[3] = {768, 1535, 2304};

    if (lane < 6) dcur[warp][lane] = 0;
    __syncwarp();

    // ---- single fused pass: packed moments + min/max + counts + precise gather
    //      (two half-warp counters per window -> halved atomic serialization) ----
    uint64_t S1p = 0, S2p = 0, S3p = 0, S4p = 0;
    float mn = INFINITY, mx = -INFINITY;
    int c0 = 0, c1 = 0, c2 = 0;
    const int half = (lane >> 4) & 1;
    #pragma unroll 4
    for (int k = 0; k < 24; k++) {
        int r = k * 4 + rg;
        uint32_t idx = base0 + (uint32_t)(r >> 5) * CHS + (uint32_t)(r & 31) * 224u;
        float4 x4 = *reinterpret_cast<const float4*>(v + idx);

        uint64_t pA = pk2(x4.x, x4.y), pB = pk2(x4.z, x4.w);
        uint64_t qA = mul2(pA, pA), qB = mul2(pB, pB);
        S1p = add2(S1p, pA); S1p = add2(S1p, pB);
        S2p = add2(S2p, qA); S2p = add2(S2p, qB);
        S3p = fma2(qA, pA, S3p); S3p = fma2(qB, pB, S3p);
        S4p = fma2(qA, qA, S4p); S4p = fma2(qB, qB, S4p);

        float xs[4] = {x4.x, x4.y, x4.z, x4.w};
        #pragma unroll
        for (int e = 0; e < 4; e++) {
            float x = xs[e];
            mn = fminf(mn, x);
            mx = fmaxf(mx, x);
            bool l0 = x < W0LO; c0 += l0;
            bool l1 = x < W1LO; c1 += l1;
            bool l2 = x < W2LO; c2 += l2;
            bool in0 = (!l0) && (x < W0HI);
            bool in1 = (!l1) && (x < W1HI);
            bool in2 = (!l2) && (x < W2HI);
            if (in0 | in1 | in2) {                 // ~17% of elements
                int wsel = in1 ? 1 : (in0 ? 0 : 2);
                int pos = atomicAdd(&dcur[warp][wsel * 2 + half], 1);
                if (pos < SEGC) cbuf[warp][wsel][half * SEGC + pos] = x;
            }
        }
    }
    float s1a, s1b, s2a, s2b, s3a, s3b, s4a, s4b;
    upk2(S1p, s1a, s1b); upk2(S2p, s2a, s2b);
    upk2(S3p, s3a, s3b); upk2(S4p, s4a, s4b);
    float S1 = wsumf(s1a + s1b), S2 = wsumf(s2a + s2b);
    float S3 = wsumf(s3a + s3b), S4 = wsumf(s4a + s4b);
    mn = wminf(mn); mx = wmaxf(mx);
    int pk = wsumi(c0 | (c1 << 16));
    c2 = wsumi(c2);
    int cla[3] = {pk & 0xFFFF, pk >> 16, c2};
    __syncwarp();

    // ---- per-window smem refinement + sort-based exact select ----
    float ql[3], qh[3];
    const unsigned ltm = (1u << lane) - 1u;
    #pragma unroll
    for (int w = 0; w < 3; w++) {
        const int g0 = dcur[warp][w * 2];
        const int g1 = dcur[warp][w * 2 + 1];
        const int g = g0 + g1;
        const bool ovf = (g0 > SEGC) | (g1 > SEGC);
        const int rmin = RMIN[w], rmax = RMAX[w];
        const int cl = cla[w];
        if (!ovf && cl <= rmin && rmax < cl + g) {
            float span = WHI[w] - WLO[w];
            float inv = span / (float)g;
            float plo2 = WLO[w] + ((float)rmin - GUARD - (float)cl) * inv;
            float phi2 = WLO[w] + ((float)rmax + GUARD + 1.0f - (float)cl) * inv;
            plo2 = fmaxf(plo2, WLO[w]);
            phi2 = fminf(phi2, WHI[w]);

            float* bw = cbuf[warp][w];
            int elo = 0, sc = 0;
            #pragma unroll 3
            for (int bidx = 0; bidx < g; bidx += 32) {
                int idx = bidx + lane;
                bool val = idx < g;
                int adr = (idx < g0) ? idx : (SEGC + idx - g0);   // virtual 2-segment index
                float x = val ? bw[adr] : 0.f;
                elo += val && (x < plo2);
                bool inb = val && (x >= plo2) && (x < phi2);
                unsigned mk = __ballot_sync(0xffffffffu, inb);
                if (inb) {
                    int pos = sc + __popc(mk & ltm);
                    if (pos < SUBCAP) sbuf[warp][pos] = x;
                }
                sc += __popc(mk);
            }
            elo = wsumi(elo);
            __syncwarp();
            int basr = cl + elo;
            if (sc <= SUBCAP && basr <= rmin && rmax < basr + sc) {
                float aa = (lane < sc) ? sbuf[warp][lane] : INFINITY;
                float bb = (lane + 32 < sc) ? sbuf[warp][lane + 32] : INFINITY;
                bitonic64(aa, bb, lane);
                ql[w] = sorted_at(aa, bb, rmin - basr);
                qh[w] = sorted_at(aa, bb, rmax - basr);
            } else {
                // rare: compact segment 1 down (staged, race-safe), then exact select
                for (int bidx = 0; bidx < g1; bidx += 32) {
                    int idx = bidx + lane;
                    float x = (idx < g1) ? bw[SEGC + idx] : 0.f;
                    __syncwarp();
                    if (idx < g1) bw[g0 + idx] = x;
                    __syncwarp();
                }
                select2c(bw, g, rmin - cl, rmax - cl, lane, &ql[w], &qh[w]);
            }
            __syncwarp();
        } else {
            ql[w] = slow_rank(v, base0, rg, rmin);
            qh[w] = (rmax == rmin) ? ql[w] : slow_rank(v, base0, rg, rmax);
        }
    }

    if (lane == 0) {
        const double n = (double)NPP;
        double s1 = S1, s2 = S2, s3 = S3, s4 = S4;
        double mean = s1 / n;
        double c2m = s2 - n * mean * mean;
        double c3m = s3 - 3.0 * mean * s2 + 2.0 * n * mean * mean * mean;
        double m2s = mean * mean;
        double c4m = s4 - 4.0 * mean * s3 + 6.0 * m2s * s2 - 3.0 * n * m2s * m2s;
        double sd = sqrt(c2m / (n - 1.0));
        double sde = sd + 1e-8;
        double energy = s2 / n;
        double rms = sqrt(energy + 1e-8);
        double i3 = 1.0 / (sde * sde * sde);
        double skew = (c3m / n) * i3;
        double kurt = (c4m / n) * i3 / sde - 3.0;
        float q25 = ql[0] * 0.25f + qh[0] * 0.75f;
        float q75 = ql[2] * 0.75f + qh[2] * 0.25f;

        float* o = out + (size_t)p * 10;
        o[0] = (float)mean; o[1] = (float)sd; o[2] = mn; o[3] = mx;
        o[4] = (float)energy; o[5] = (float)rms; o[6] = (float)skew;
        o[7] = (float)kurt; o[8] = ql[1]; o[9] = q75 - q25;
    }
}

__device__ __forceinline__ int tau_t(int t) {
    int c = 0;
    if (t + 1 < TT) c++;
    if (t - 1 >= 0) c++;
    if (t + 2 < TT) c++;
    if (t - 2 >= 0) c++;
    return c;
}

__global__ void edge_kernel(float* __restrict__ out)
{
    int node = blockIdx.x * blockDim.x + threadIdx.x;
    if (node >= NODES) return;
    int t = node / NPF;
    int rem = node % NPF;
    int i = rem / GW;
    int j = rem % GW;

    int mt = t < 30 ? t : 30;
    int cum_tau = (t > 0 ? 2 : 0) + (t > 1 ? 3 : 0)
                + 4 * (mt > 2 ? (mt - 2) : 0) + (t > 30 ? 3 : 0);
    int taut = tau_t(t);
    int rowpref = (i == 0) ? 0 : (31 + 50 * (i - 1));
    int ci = (i == 0 || i == GH - 1) ? 2 : 3;
    int cumcj = (j > 0 ? 2 : 0) + 3 * (j > 1 ? (j - 1) : 0);
    int sp = rowpref + ci * cumcj - j;
    int off = 312 * t + 49 * cum_tau + sp + rem * taut;

    const int di[8] = {-1,-1,-1, 0, 0, 1, 1, 1};
    const int dj[8] = {-1, 0, 1,-1, 1,-1, 0, 1};
    int e = off;
    float fnode = (float)node;
    #pragma unroll
    for (int q = 0; q < 8; q++) {
        int ni = i + di[q], nj = j + dj[q];
        if (ni >= 0 && ni < GH && nj >= 0 && nj < GW) {
            out[e]         = fnode;
            out[NEDGE + e] = (float)(t * NPF + ni * GW + nj);
            e++;
        }
    }
    const int dts[4] = {1, -1, 2, -2};
    #pragma unroll
    for (int q = 0; q < 4; q++) {
        int tt2 = t + dts[q];
        if (tt2 >= 0 && tt2 < TT) {
            out[e]         = fnode;
            out[NEDGE + e] = (float)(tt2 * NPF + i * GW + j);
            e++;
        }
    }
}

extern "C" void kernel_launch(void* const* d_in, const int* in_sizes, int n_in,
                              void* d_out, int out_size)
{
    const float* video = (const float*)d_in[0];
    float* out = (float*)d_out;

    if (out_size >= XFLOATS + 2 * NEDGE) {
        edge_kernel<<<(NODES + 255) / 256, 256>>>(out + XFLOATS);
    }
    feat_kernel<<<NPATCH / PPB, 32 * PPB>>>(video, out);
}